// round 16
// baseline (speedup 1.0000x reference)
#include <cuda_runtime.h>
#include <cuda_fp16.h>
#include <math.h>
#include <stdint.h>

// Problem constants
#define BB 128      // batch
#define TT 128      // time steps
#define FF 128      // features
#define DD 512      // hidden
#define NG 2048     // 4*D
#define KC 128      // K-chunk in ELEMENTS (fp16 -> 8 k16 MMA steps)
#define NSTAGE 3
#define NTH 256     // 8 warps per CTA; 2 CTAs/SM

// block tile: M=32 (4 M-quarters) x N=32 (64 N-groups) -> grid 256 (2 CTAs/SM)
#define BM 32
#define BN 32

// halves per row, padded: word stride 68 == 4 mod 32 -> conflict-free fragment LDS
#define ALDH 136
#define BLDH 136
#define A_ST_H (BM*ALDH)              // 4352 halves
#define B_ST_H (BN*BLDH)              // 4352 halves
#define STAGE_H (A_ST_H + B_ST_H)     // 8704 halves
#define SMEM_BYTES (NSTAGE*STAGE_H*2) // 52224 B  (x2 CTAs = 104448 < 228KB)
#define ZLD 34                        // fp32 z-tile row stride

// ---- scratch (device globals; no allocation allowed) ----
__device__ __half g_h [BB*DD];
__device__ __half g_h0[BB*DD];
__device__ __half g_hA[BB*DD];
__device__ __half g_hB[BB*DD];
__device__ float  g_c [BB*DD];
__device__ float  g_c0[BB*DD];
__device__ float  g_cA[BB*DD];
__device__ float  g_cB[BB*DD];
// permuted + fp16-rounded weights: [n][k], n = d*4+gate
__device__ __half g_pEW0[NG*FF];
__device__ __half g_pEU0[NG*DD];
__device__ __half g_pW1s[NG*DD];
__device__ __half g_pDW0[NG*FF];
__device__ __half g_pDU0[NG*DD];
__device__ __half g_pDW1[NG*DD];
__device__ __half g_pDU1[NG*DD];
// permuted biases (fp32)
__device__ float g_pbE0[NG];
__device__ float g_pbE1[NG];
__device__ float g_pbD0[NG];
__device__ float g_pbD1[NG];
// fp16-rounded inputs / feedback
__device__ __half g_encR[BB*TT*FF];
__device__ __half g_x0R [BB*FF];
__device__ __half g_xfb [BB*FF];

// ---- helpers ----
__device__ __forceinline__ float sigmoidf_(float x) { return 1.0f / (1.0f + expf(-x)); }

__device__ __forceinline__ unsigned smem_u32(const void* p) {
    return (unsigned)__cvta_generic_to_shared(p);
}

#define CP_ASYNC16(dst_u32, src_ptr) \
    asm volatile("cp.async.cg.shared.global [%0], [%1], 16;\n" :: "r"(dst_u32), "l"(src_ptr))
#define CP_COMMIT() asm volatile("cp.async.commit_group;\n" ::: "memory")
#define CP_WAIT1()  asm volatile("cp.async.wait_group 1;\n" ::: "memory")

// m16n8k16 fp16 MMA, fp32 accumulate (baseline PTX, compiles at compute_103)
__device__ __forceinline__ void mma_f16(float* d,
    unsigned a0, unsigned a1, unsigned a2, unsigned a3, unsigned b0, unsigned b1)
{
    asm volatile(
        "mma.sync.aligned.m16n8k16.row.col.f32.f16.f16.f32 "
        "{%0,%1,%2,%3}, {%4,%5,%6,%7}, {%8,%9}, {%0,%1,%2,%3};"
        : "+f"(d[0]), "+f"(d[1]), "+f"(d[2]), "+f"(d[3])
        : "r"(a0), "r"(a1), "r"(a2), "r"(a3), "r"(b0), "r"(b1));
}

// ================= fused preprocessing (ONE kernel = launch #0) =================
__device__ __forceinline__ void scatter_perm_h(const float* __restrict__ src,
                                               __half* __restrict__ dst, int K, int kshift,
                                               int gt, int NT, const float* __restrict__ src2)
{
    for (int i = gt; i < NG * K; i += NT) {
        int k = i & (K - 1);
        int n = i >> kshift;
        int g = n & 3, d = n >> 2;
        size_t si = (size_t)k * NG + g * DD + d;
        float v = src[si];
        if (src2) v += src2[si];
        dst[i] = __float2half_rn(v);
    }
}

__global__ void preproc_kernel(
    const float* __restrict__ enc_in, const float* __restrict__ dec_in,
    const float* __restrict__ eW0, const float* __restrict__ eU0,
    const float* __restrict__ eb0, const float* __restrict__ eW1,
    const float* __restrict__ eU1, const float* __restrict__ eb1,
    const float* __restrict__ dW0, const float* __restrict__ dU0,
    const float* __restrict__ db0, const float* __restrict__ dW1,
    const float* __restrict__ dU1, const float* __restrict__ db1)
{
    const int gt = blockIdx.x * blockDim.x + threadIdx.x;
    const int NT = gridDim.x * blockDim.x;

    const __half hz = __float2half_rn(0.f);
    for (int i = gt; i < BB * DD; i += NT) {
        g_h[i] = hz; g_c[i] = 0.f;
    }
    for (int i = gt; i < BB * TT * FF; i += NT) g_encR[i] = __float2half_rn(enc_in[i]);
    for (int i = gt; i < BB * FF; i += NT) {
        int b = i >> 7, f = i & 127;
        g_x0R[i] = __float2half_rn(dec_in[(size_t)b * TT * FF + f]);
    }
    scatter_perm_h(eW0, g_pEW0, FF, 7, gt, NT, nullptr);
    scatter_perm_h(dW0, g_pDW0, FF, 7, gt, NT, nullptr);
    scatter_perm_h(eU0, g_pEU0, DD, 9, gt, NT, nullptr);
    scatter_perm_h(eW1, g_pW1s, DD, 9, gt, NT, eU1);    // fused W1+U1
    scatter_perm_h(dU0, g_pDU0, DD, 9, gt, NT, nullptr);
    scatter_perm_h(dW1, g_pDW1, DD, 9, gt, NT, nullptr);
    scatter_perm_h(dU1, g_pDU1, DD, 9, gt, NT, nullptr);
    for (int n = gt; n < NG; n += NT) {
        int si = (n & 3) * DD + (n >> 2);
        g_pbE0[n] = eb0[si]; g_pbE1[n] = eb1[si];
        g_pbD0[n] = db0[si]; g_pbD1[n] = db1[si];
    }
}

// ================= tensor-core LSTM cell (mma.sync fp16 -> fp32) =================
// z[128x2048] = X@BW^T (K1 halves) + H@BU^T (K2) + pbias; BW/BU permuted [n][k].
// grid 256 = (4 M-quarters) x (64 N-groups): 2 CTAs/SM -> two independent
// barrier/wait domains per SM fill each other's stall slots.
// 256 thr = 8 warps (2M x 4N), warp tile 16x8. KC=128 = 8 k16 MMA steps,
// dual accumulators (even/odd ks) halve the serial HMMA chain.
__global__ __launch_bounds__(NTH, 2)
void lstm_cell_mma(const __half* __restrict__ X, int ldx, int K1,
                   const __half* __restrict__ BW,
                   const __half* __restrict__ H, const __half* __restrict__ BU, int K2,
                   const float* __restrict__ pbias, const float* __restrict__ cin,
                   __half* __restrict__ hout, float* __restrict__ cout)
{
    extern __shared__ __align__(16) __half smh[];

    const int tid   = threadIdx.x;
    const int lane  = tid & 31;
    const int wid   = tid >> 5;          // 0..7
    const int gid   = lane >> 2;
    const int tidg  = lane & 3;
    const int warpM = wid & 1;           // m-rows base = warpM*16
    const int warpN = wid >> 1;          // n-cols base = warpN*8
    const int mbase = (blockIdx.x & 3) * BM;
    const int nb    = blockIdx.x >> 2;
    const int nb32  = nb * BN;

    const int nck = (K1 + K2) / KC;

    // ---- staging: chunk ck -> stage s ----
    auto stage = [&](int ck, int s) {
        const int k0 = ck * KC;
        const __half* Ap; int lda_, kA; const __half* Bp; int kB, ldb;
        if (k0 < K1) { Ap = X; lda_ = ldx; kA = k0;      Bp = BW; kB = k0;      ldb = K1; }
        else         { Ap = H; lda_ = DD;  kA = k0 - K1; Bp = BU; kB = k0 - K1; ldb = K2; }
        // A: 32 rows x 16 quads(8 halves) = 512 quads -> 2 per thread
        {
            const int row = tid >> 3, q0 = tid & 7;
            const __half* src = Ap + (size_t)(mbase + row) * lda_ + kA + q0 * 8;
            const unsigned dst = smem_u32(smh + s * STAGE_H + row * ALDH + q0 * 8);
            CP_ASYNC16(dst, src);
            CP_ASYNC16(dst + 64 * 2, src + 64);   // quad q0+8
        }
        // B: 32 rows x 16 quads = 512 quads -> 2 per thread
        {
            const int row = tid >> 3, q0 = tid & 7;
            const __half* src = Bp + (size_t)(nb32 + row) * ldb + kB + q0 * 8;
            const unsigned dst = smem_u32(smh + s * STAGE_H + A_ST_H + row * BLDH + q0 * 8);
            CP_ASYNC16(dst, src);
            CP_ASYNC16(dst + 64 * 2, src + 64);
        }
    };

    float accE[4] = {0.f, 0.f, 0.f, 0.f};
    float accO[4] = {0.f, 0.f, 0.f, 0.f};

    // prologue: 2 chunks in flight
    stage(0, 0); CP_COMMIT();
    if (nck > 1) stage(1, 1);
    CP_COMMIT();

    int sRead = 0;
    for (int ck = 0; ck < nck; ++ck) {
        CP_WAIT1();            // newest group may be pending; chunk ck has landed
        __syncthreads();       // one sync per chunk

        // view stage as 32-bit words; word stride per row = ALDH/2 = 68
        const unsigned* As = (const unsigned*)(smh + sRead * STAGE_H);
        const unsigned* Bs = As + A_ST_H / 2;

        #pragma unroll
        for (int ks = 0; ks < 8; ++ks) {
            const int kb = ks * 8;     // word offset: 16 halves per ks
            const int rb = warpM * 16;
            unsigned a0 = As[(rb + gid    ) * 68 + kb + tidg    ];
            unsigned a1 = As[(rb + gid + 8) * 68 + kb + tidg    ];
            unsigned a2 = As[(rb + gid    ) * 68 + kb + tidg + 4];
            unsigned a3 = As[(rb + gid + 8) * 68 + kb + tidg + 4];
            const int nbase = warpN * 8;
            unsigned b0 = Bs[(nbase + gid) * 68 + kb + tidg    ];
            unsigned b1 = Bs[(nbase + gid) * 68 + kb + tidg + 4];
            mma_f16((ks & 1) ? accO : accE, a0, a1, a2, a3, b0, b1);
        }

        // stage chunk ck+2 into buffer (ck+2)%3 == (ck-1)%3: its readers finished
        // iteration ck-1 before this iteration's top sync -> safe
        if (ck + 2 < nck) {
            int sW = sRead - 1; if (sW < 0) sW = NSTAGE - 1;
            stage(ck + 2, sW);
        }
        CP_COMMIT();           // one group per iteration (may be empty)

        if (++sRead == NSTAGE) sRead = 0;
    }
    __syncthreads();           // all compute done before smem reuse (z-tile)

    // ---- epilogue: fragments -> fp32 z-tile in smem -> gates ----
    float* zs = (float*)smh;   // 32 x ZLD floats
    {
        const int row0 = warpM * 16 + gid;
        const int col0 = warpN * 8 + 2 * tidg;
        zs[(row0    ) * ZLD + col0    ] = accE[0] + accO[0];
        zs[(row0    ) * ZLD + col0 + 1] = accE[1] + accO[1];
        zs[(row0 + 8) * ZLD + col0    ] = accE[2] + accO[2];
        zs[(row0 + 8) * ZLD + col0 + 1] = accE[3] + accO[3];
    }
    __syncthreads();

    {
        const int rl = tid >> 3;            // local batch row 0..31
        const int dl = tid & 7;             // local d-col 0..7
        const int r  = mbase + rl;
        const int nl = dl * 4;
        const int col = nb * 8 + dl;
        float zi = zs[rl * ZLD + nl + 0] + pbias[nb32 + nl + 0];
        float zf = zs[rl * ZLD + nl + 1] + pbias[nb32 + nl + 1];
        float zg = zs[rl * ZLD + nl + 2] + pbias[nb32 + nl + 2];
        float zo = zs[rl * ZLD + nl + 3] + pbias[nb32 + nl + 3];
        float i  = sigmoidf_(zi);
        float f  = sigmoidf_(zf);
        float g  = fmaxf(zg, 0.f);
        float o  = sigmoidf_(zo);
        float c2 = f * cin[r * DD + col] + i * g;
        cout[r * DD + col] = c2;
        hout[r * DD + col] = __float2half_rn(o * fmaxf(c2, 0.f));
    }
}

// ================= dense =================
__global__ __launch_bounds__(128, 1) void dense_kernel(
    const __half* __restrict__ H, const float* __restrict__ Wd,
    const float* __restrict__ bd, float* __restrict__ out, __half* __restrict__ xfb)
{
    __shared__ float hs[DD];
    const int row = blockIdx.x;
    const int col = threadIdx.x;
    const __half* h = H + (size_t)row * DD;
    #pragma unroll
    for (int k = col; k < DD; k += 128) hs[k] = __half2float(h[k]);
    __syncthreads();
    float a0 = 0.f, a1 = 0.f, a2 = 0.f, a3 = 0.f;
    #pragma unroll 4
    for (int k = 0; k < DD; k += 4) {
        a0 += hs[k + 0] * Wd[(size_t)(k + 0) * FF + col];
        a1 += hs[k + 1] * Wd[(size_t)(k + 1) * FF + col];
        a2 += hs[k + 2] * Wd[(size_t)(k + 2) * FF + col];
        a3 += hs[k + 3] * Wd[(size_t)(k + 3) * FF + col];
    }
    float v = (a0 + a1) + (a2 + a3) + bd[col];
    out[(size_t)row * TT * FF + col] = v;
    xfb[row * FF + col] = __float2half_rn(v);
}

extern "C" void kernel_launch(void* const* d_in, const int* in_sizes, int n_in,
                              void* d_out, int out_size)
{
    const float* enc_in  = (const float*)d_in[0];
    const float* dec_in  = (const float*)d_in[1];
    const float* enc_W0  = (const float*)d_in[2];
    const float* enc_U0  = (const float*)d_in[3];
    const float* enc_b0  = (const float*)d_in[4];
    const float* enc_W1  = (const float*)d_in[5];
    const float* enc_U1  = (const float*)d_in[6];
    const float* enc_b1  = (const float*)d_in[7];
    const float* dec_W0  = (const float*)d_in[8];
    const float* dec_U0  = (const float*)d_in[9];
    const float* dec_b0  = (const float*)d_in[10];
    const float* dec_W1  = (const float*)d_in[11];
    const float* dec_U1  = (const float*)d_in[12];
    const float* dec_b1  = (const float*)d_in[13];
    const float* dense_W = (const float*)d_in[14];
    const float* dense_b = (const float*)d_in[15];
    float* out = (float*)d_out;

    cudaFuncSetAttribute(lstm_cell_mma, cudaFuncAttributeMaxDynamicSharedMemorySize, SMEM_BYTES);

    __half *h, *h0, *hA, *hB, *encR, *x0R, *xfb;
    float  *c, *c0, *cA, *cB;
    __half *pEW0, *pEU0, *pW1s, *pDW0, *pDU0, *pDW1, *pDU1;
    float  *pbE0, *pbE1, *pbD0, *pbD1;
    cudaGetSymbolAddress((void**)&h,    g_h);
    cudaGetSymbolAddress((void**)&h0,   g_h0);
    cudaGetSymbolAddress((void**)&hA,   g_hA);
    cudaGetSymbolAddress((void**)&hB,   g_hB);
    cudaGetSymbolAddress((void**)&c,    g_c);
    cudaGetSymbolAddress((void**)&c0,   g_c0);
    cudaGetSymbolAddress((void**)&cA,   g_cA);
    cudaGetSymbolAddress((void**)&cB,   g_cB);
    cudaGetSymbolAddress((void**)&pEW0, g_pEW0);
    cudaGetSymbolAddress((void**)&pEU0, g_pEU0);
    cudaGetSymbolAddress((void**)&pW1s, g_pW1s);
    cudaGetSymbolAddress((void**)&pDW0, g_pDW0);
    cudaGetSymbolAddress((void**)&pDU0, g_pDU0);
    cudaGetSymbolAddress((void**)&pDW1, g_pDW1);
    cudaGetSymbolAddress((void**)&pDU1, g_pDU1);
    cudaGetSymbolAddress((void**)&pbE0, g_pbE0);
    cudaGetSymbolAddress((void**)&pbE1, g_pbE1);
    cudaGetSymbolAddress((void**)&pbD0, g_pbD0);
    cudaGetSymbolAddress((void**)&pbD1, g_pbD1);
    cudaGetSymbolAddress((void**)&encR, g_encR);
    cudaGetSymbolAddress((void**)&x0R,  g_x0R);
    cudaGetSymbolAddress((void**)&xfb,  g_xfb);

    // launch #0: ALL preprocessing in one kernel (cells start at launch #1)
    preproc_kernel<<<1024, 256>>>(enc_in, dec_in,
                                  enc_W0, enc_U0, enc_b0, enc_W1, enc_U1, enc_b1,
                                  dec_W0, dec_U0, dec_b0, dec_W1, dec_U1, dec_b1);

    const int ldt = TT * FF;

    // ---------------- Encoder: 128 steps, 2 layers ----------------
    for (int t = 0; t < TT; ++t) {
        lstm_cell_mma<<<256, NTH, SMEM_BYTES>>>(encR + (size_t)t * FF, ldt, FF, pEW0,
                                                h, pEU0, DD,
                                                pbE0, c, h0, c0);
        // layer 1: x == h == h0 => z = h0@(W1+U1)
        lstm_cell_mma<<<256, NTH, SMEM_BYTES>>>(h0, DD, DD, pW1s,
                                                (const __half*)nullptr, (const __half*)nullptr, 0,
                                                pbE1, c0, h, c);
    }

    // ---------------- Decoder: 128 steps, 2 layers + dense ----------------
    for (int t = 0; t < TT; ++t) {
        const __half* hcur = (t == 0) ? h : ((t & 1) ? hA : hB);
        const float*  ccur = (t == 0) ? c : ((t & 1) ? cA : cB);
        __half* hnext = (t & 1) ? hB : hA;
        float*  cnext = (t & 1) ? cB : cA;

        const __half* X = (t == 0) ? x0R : xfb;   // fp16-rounded feedback

        // layer 0: reads OLD h,c (reference quirk); its c2 discarded
        lstm_cell_mma<<<256, NTH, SMEM_BYTES>>>(X, FF, FF, pDW0,
                                                hcur, pDU0, DD,
                                                pbD0, ccur, h0, c0);
        // layer 1: x = layer0 h, h/c = OLD carry
        lstm_cell_mma<<<256, NTH, SMEM_BYTES>>>(h0, DD, DD, pDW1,
                                                hcur, pDU1, DD,
                                                pbD1, ccur, hnext, cnext);
        // dense: exact fp32 -> out[:, T-1-t, :]; fp16-rounded copy -> xfb
        dense_kernel<<<128, 128>>>(hnext, dense_W, dense_b,
                                   out + (size_t)(TT - 1 - t) * FF, xfb);
    }
}

// round 17
// speedup vs baseline: 1.0586x; 1.0586x over previous
#include <cuda_runtime.h>
#include <cuda_fp16.h>
#include <math.h>
#include <stdint.h>

// Problem constants
#define BB 128
#define TT 128
#define FF 128
#define DD 512
#define NG 2048
#define KC 128      // K-chunk elements (8 k16 MMA steps)
#define NSTAGE 3
#define NTH 512     // 16 warps
#define NBLK 128    // grid: 2 M-halves x 64 N-groups; all resident (1 CTA/SM)

#define BM 64
#define BN 32

#define ALDH 136
#define BLDH 136
#define A_ST_H (BM*ALDH)              // 8704 halves
#define B_ST_H (BN*BLDH)              // 4352 halves
#define STAGE_H (A_ST_H + B_ST_H)     // 13056 halves
#define SMEM_BYTES (NSTAGE*STAGE_H*2) // 78336 B
#define ZLD 34

// ---- scratch ----
__device__ __half g_h [BB*DD];
__device__ __half g_h0[BB*DD];
__device__ __half g_hA[BB*DD];
__device__ __half g_hB[BB*DD];
__device__ float  g_c [BB*DD];
__device__ float  g_c0[BB*DD];
__device__ float  g_cA[BB*DD];
__device__ float  g_cB[BB*DD];
__device__ __half g_pEW0[NG*FF];
__device__ __half g_pEU0[NG*DD];
__device__ __half g_pW1s[NG*DD];
__device__ __half g_pDW0[NG*FF];
__device__ __half g_pDU0[NG*DD];
__device__ __half g_pDW1[NG*DD];
__device__ __half g_pDU1[NG*DD];
__device__ float g_pbE0[NG];
__device__ float g_pbE1[NG];
__device__ float g_pbD0[NG];
__device__ float g_pbD1[NG];
__device__ __half g_encR[BB*TT*FF];
__device__ __half g_x0R [BB*FF];
__device__ __half g_xfb [BB*FF];
// grid barrier: count and generation on SEPARATE 128B lines; gen is monotone
// across launches (no reset needed)
__device__ __align__(128) unsigned g_bcnt;
__device__ __align__(128) unsigned g_bgen;

// ---- helpers ----
__device__ __forceinline__ float sigmoidf_(float x) { return 1.0f / (1.0f + expf(-x)); }

__device__ __forceinline__ unsigned smem_u32(const void* p) {
    return (unsigned)__cvta_generic_to_shared(p);
}

#define CP_ASYNC16(dst_u32, src_ptr) \
    asm volatile("cp.async.cg.shared.global [%0], [%1], 16;\n" :: "r"(dst_u32), "l"(src_ptr))
#define CP_COMMIT() asm volatile("cp.async.commit_group;\n" ::: "memory")
#define CP_WAIT1()  asm volatile("cp.async.wait_group 1;\n" ::: "memory")

__device__ __forceinline__ void mma_f16(float* d,
    unsigned a0, unsigned a1, unsigned a2, unsigned a3, unsigned b0, unsigned b1)
{
    asm volatile(
        "mma.sync.aligned.m16n8k16.row.col.f32.f16.f16.f32 "
        "{%0,%1,%2,%3}, {%4,%5,%6,%7}, {%8,%9}, {%0,%1,%2,%3};"
        : "+f"(d[0]), "+f"(d[1]), "+f"(d[2]), "+f"(d[3])
        : "r"(a0), "r"(a1), "r"(a2), "r"(a3), "r"(b0), "r"(b1));
}

__device__ __forceinline__ unsigned ld_vol(const unsigned* p) {
    unsigned v;
    asm volatile("ld.volatile.global.u32 %0, [%1];" : "=r"(v) : "l"(p));
    return v;
}

// generation-based grid barrier (valid across kernel launches)
__device__ __forceinline__ void grid_bar()
{
    __threadfence();             // every thread: publish pre-barrier writes
    __syncthreads();
    if (threadIdx.x == 0) {
        unsigned my = ld_vol(&g_bgen);     // snapshot BEFORE arriving
        if (atomicAdd(&g_bcnt, 1u) == NBLK - 1) {
            g_bcnt = 0;
            __threadfence();               // cnt reset visible before gen bump
            atomicExch(&g_bgen, my + 1);
        } else {
            while (ld_vol(&g_bgen) == my) __nanosleep(64);
        }
    }
    __syncthreads();
}

// ================= fused preprocessing (launch #0) =================
__device__ __forceinline__ void scatter_perm_h(const float* __restrict__ src,
                                               __half* __restrict__ dst, int K, int kshift,
                                               int gt, int NT, const float* __restrict__ src2)
{
    for (int i = gt; i < NG * K; i += NT) {
        int k = i & (K - 1);
        int n = i >> kshift;
        int g = n & 3, d = n >> 2;
        size_t si = (size_t)k * NG + g * DD + d;
        float v = src[si];
        if (src2) v += src2[si];
        dst[i] = __float2half_rn(v);
    }
}

__global__ void preproc_kernel(
    const float* __restrict__ enc_in, const float* __restrict__ dec_in,
    const float* __restrict__ eW0, const float* __restrict__ eU0,
    const float* __restrict__ eb0, const float* __restrict__ eW1,
    const float* __restrict__ eU1, const float* __restrict__ eb1,
    const float* __restrict__ dW0, const float* __restrict__ dU0,
    const float* __restrict__ db0, const float* __restrict__ dW1,
    const float* __restrict__ dU1, const float* __restrict__ db1)
{
    const int gt = blockIdx.x * blockDim.x + threadIdx.x;
    const int NT = gridDim.x * blockDim.x;

    if (gt == 0) { g_bcnt = 0; g_bgen = 0; }

    const __half hz = __float2half_rn(0.f);
    for (int i = gt; i < BB * DD; i += NT) { g_h[i] = hz; g_c[i] = 0.f; }
    for (int i = gt; i < BB * TT * FF; i += NT) g_encR[i] = __float2half_rn(enc_in[i]);
    for (int i = gt; i < BB * FF; i += NT) {
        int b = i >> 7, f = i & 127;
        g_x0R[i] = __float2half_rn(dec_in[(size_t)b * TT * FF + f]);
    }
    scatter_perm_h(eW0, g_pEW0, FF, 7, gt, NT, nullptr);
    scatter_perm_h(dW0, g_pDW0, FF, 7, gt, NT, nullptr);
    scatter_perm_h(eU0, g_pEU0, DD, 9, gt, NT, nullptr);
    scatter_perm_h(eW1, g_pW1s, DD, 9, gt, NT, eU1);    // fused W1+U1
    scatter_perm_h(dU0, g_pDU0, DD, 9, gt, NT, nullptr);
    scatter_perm_h(dW1, g_pDW1, DD, 9, gt, NT, nullptr);
    scatter_perm_h(dU1, g_pDU1, DD, 9, gt, NT, nullptr);
    for (int n = gt; n < NG; n += NT) {
        int si = (n & 3) * DD + (n >> 2);
        g_pbE0[n] = eb0[si]; g_pbE1[n] = eb1[si];
        g_pbD0[n] = db0[si]; g_pbD1[n] = db1[si];
    }
}

// ================= LSTM cell device function (R15 body) =================
// z[128x2048] = X@BW^T (K1) + H@BU^T (K2) + pbias; gates; hout fp16, cout fp32.
// cin read via __ldcg (may be written by other blocks pre-barrier this launch).
__device__ __forceinline__ void run_cell(__half* smh,
    const __half* __restrict__ X, int ldx, int K1, const __half* __restrict__ BW,
    const __half* __restrict__ H, const __half* __restrict__ BU, int K2,
    const float* __restrict__ pbias, const float* __restrict__ cin,
    __half* __restrict__ hout, float* __restrict__ cout, bool writeC)
{
    const int tid   = threadIdx.x;
    const int lane  = tid & 31;
    const int wid   = tid >> 5;
    const int gid   = lane >> 2;
    const int tidg  = lane & 3;
    const int warpM = wid & 3;
    const int warpN = wid >> 2;
    const int mbase = (blockIdx.x & 1) * BM;
    const int nb    = blockIdx.x >> 1;
    const int nb32  = nb * BN;

    const int nck = (K1 + K2) / KC;

    auto stage = [&](int ck, int s) {
        const int k0 = ck * KC;
        const __half* Ap; int lda_, kA; const __half* Bp; int kB, ldb;
        if (k0 < K1) { Ap = X; lda_ = ldx; kA = k0;      Bp = BW; kB = k0;      ldb = K1; }
        else         { Ap = H; lda_ = DD;  kA = k0 - K1; Bp = BU; kB = k0 - K1; ldb = K2; }
        {
            const int row = tid >> 3, q0 = tid & 7;
            const __half* src = Ap + (size_t)(mbase + row) * lda_ + kA + q0 * 8;
            const unsigned dst = smem_u32(smh + s * STAGE_H + row * ALDH + q0 * 8);
            CP_ASYNC16(dst, src);
            CP_ASYNC16(dst + 64 * 2, src + 64);
        }
        {
            const int row = tid >> 4, q = tid & 15;
            const __half* src = Bp + (size_t)(nb32 + row) * ldb + kB + q * 8;
            const unsigned dst = smem_u32(smh + s * STAGE_H + A_ST_H + row * BLDH + q * 8);
            CP_ASYNC16(dst, src);
        }
    };

    float acc[4] = {0.f, 0.f, 0.f, 0.f};

    stage(0, 0); CP_COMMIT();
    if (nck > 1) stage(1, 1);
    CP_COMMIT();

    int sRead = 0;
    for (int ck = 0; ck < nck; ++ck) {
        CP_WAIT1();
        __syncthreads();

        const unsigned* As = (const unsigned*)(smh + sRead * STAGE_H);
        const unsigned* Bs = As + A_ST_H / 2;

        #pragma unroll
        for (int ks = 0; ks < 8; ++ks) {
            const int kb = ks * 8;
            const int rb = warpM * 16;
            unsigned a0 = As[(rb + gid    ) * 68 + kb + tidg    ];
            unsigned a1 = As[(rb + gid + 8) * 68 + kb + tidg    ];
            unsigned a2 = As[(rb + gid    ) * 68 + kb + tidg + 4];
            unsigned a3 = As[(rb + gid + 8) * 68 + kb + tidg + 4];
            const int nbase = warpN * 8;
            unsigned b0 = Bs[(nbase + gid) * 68 + kb + tidg    ];
            unsigned b1 = Bs[(nbase + gid) * 68 + kb + tidg + 4];
            mma_f16(acc, a0, a1, a2, a3, b0, b1);
        }

        if (ck + 2 < nck) {
            int sW = sRead - 1; if (sW < 0) sW = NSTAGE - 1;
            stage(ck + 2, sW);
        }
        CP_COMMIT();

        if (++sRead == NSTAGE) sRead = 0;
    }
    __syncthreads();

    float* zs = (float*)smh;
    {
        const int row0 = warpM * 16 + gid;
        const int col0 = warpN * 8 + 2 * tidg;
        zs[(row0    ) * ZLD + col0    ] = acc[0];
        zs[(row0    ) * ZLD + col0 + 1] = acc[1];
        zs[(row0 + 8) * ZLD + col0    ] = acc[2];
        zs[(row0 + 8) * ZLD + col0 + 1] = acc[3];
    }
    __syncthreads();

    {
        const int rl = tid >> 3;
        const int dl = tid & 7;
        const int r  = mbase + rl;
        const int nl = dl * 4;
        const int col = nb * 8 + dl;
        float zi = zs[rl * ZLD + nl + 0] + pbias[nb32 + nl + 0];
        float zf = zs[rl * ZLD + nl + 1] + pbias[nb32 + nl + 1];
        float zg = zs[rl * ZLD + nl + 2] + pbias[nb32 + nl + 2];
        float zo = zs[rl * ZLD + nl + 3] + pbias[nb32 + nl + 3];
        float i  = sigmoidf_(zi);
        float f  = sigmoidf_(zf);
        float g  = fmaxf(zg, 0.f);
        float o  = sigmoidf_(zo);
        float c2 = f * __ldcg(cin + r * DD + col) + i * g;
        if (writeC) cout[r * DD + col] = c2;
        hout[r * DD + col] = __float2half_rn(o * fmaxf(c2, 0.f));
    }
}

// ================= fused encoder step: L0 -> grid_bar -> L1 =================
__global__ __launch_bounds__(NTH, 1)
void enc_step_kernel(int t)
{
    extern __shared__ __align__(16) __half smh[];

    run_cell(smh, g_encR + (size_t)t * FF, TT * FF, FF, g_pEW0,
             g_h, g_pEU0, DD, g_pbE0, g_c, g_h0, g_c0, true);
    grid_bar();
    // layer 1: x == h == h0 => z = h0@(W1+U1); cin = c0 (written pre-bar by others)
    run_cell(smh, g_h0, DD, DD, g_pW1s,
             (const __half*)nullptr, (const __half*)nullptr, 0,
             g_pbE1, g_c0, g_h, g_c, true);
}

// ================= fused decoder step: L0 -> bar -> L1 -> bar -> dense =====
__global__ __launch_bounds__(NTH, 1)
void dec_step_kernel(int t, const float* __restrict__ dW,
                     const float* __restrict__ db_, float* __restrict__ out)
{
    extern __shared__ __align__(16) __half smh[];

    const __half* hcur = (t == 0) ? g_h : ((t & 1) ? g_hA : g_hB);
    const float*  ccur = (t == 0) ? g_c : ((t & 1) ? g_cA : g_cB);
    __half* hnext = (t & 1) ? g_hB : g_hA;
    float*  cnext = (t & 1) ? g_cB : g_cA;
    const __half* X = (t == 0) ? g_x0R : g_xfb;

    // layer 0: reads OLD h,c (reference quirk); its c2 is never read -> skip store
    run_cell(smh, X, FF, FF, g_pDW0, hcur, g_pDU0, DD,
             g_pbD0, ccur, g_h0, (float*)nullptr, false);
    grid_bar();
    // layer 1: x = layer0 h (h0, via cp.async L2), h/c = OLD carry
    run_cell(smh, g_h0, DD, DD, g_pDW1, hcur, g_pDU1, DD,
             g_pbD1, ccur, hnext, cnext, true);
    grid_bar();

    // ---- dense: block = batch row; out exact fp32; xfb fp16 feedback ----
    {
        const int tid = threadIdx.x;
        const int row = blockIdx.x;
        float* hs = (float*)smh;         // 512 floats
        float* ps = hs + DD;             // 512 partials
        const __half* hrow = hnext + (size_t)row * DD;
        hs[tid] = __half2float(__ldcg(hrow + tid));
        __syncthreads();

        const int col = tid & 127;
        const int q   = tid >> 7;        // K quarter 0..3
        const float* wp = dW + (size_t)(q * 128) * FF + col;
        float a0 = 0.f, a1 = 0.f;
        #pragma unroll 8
        for (int k = 0; k < 128; k += 2) {
            a0 += hs[q * 128 + k    ] * wp[(size_t)(k    ) * FF];
            a1 += hs[q * 128 + k + 1] * wp[(size_t)(k + 1) * FF];
        }
        ps[tid] = a0 + a1;
        __syncthreads();
        if (q == 0) {
            float v = ps[col] + ps[128 + col] + ps[256 + col] + ps[384 + col] + db_[col];
            out[((size_t)row * TT + (TT - 1 - t)) * FF + col] = v;
            g_xfb[row * FF + col] = __float2half_rn(v);
        }
    }
}

extern "C" void kernel_launch(void* const* d_in, const int* in_sizes, int n_in,
                              void* d_out, int out_size)
{
    const float* enc_in  = (const float*)d_in[0];
    const float* dec_in  = (const float*)d_in[1];
    const float* enc_W0  = (const float*)d_in[2];
    const float* enc_U0  = (const float*)d_in[3];
    const float* enc_b0  = (const float*)d_in[4];
    const float* enc_W1  = (const float*)d_in[5];
    const float* enc_U1  = (const float*)d_in[6];
    const float* enc_b1  = (const float*)d_in[7];
    const float* dec_W0  = (const float*)d_in[8];
    const float* dec_U0  = (const float*)d_in[9];
    const float* dec_b0  = (const float*)d_in[10];
    const float* dec_W1  = (const float*)d_in[11];
    const float* dec_U1  = (const float*)d_in[12];
    const float* dec_b1  = (const float*)d_in[13];
    const float* dense_W = (const float*)d_in[14];
    const float* dense_b = (const float*)d_in[15];
    float* out = (float*)d_out;

    cudaFuncSetAttribute(enc_step_kernel, cudaFuncAttributeMaxDynamicSharedMemorySize, SMEM_BYTES);
    cudaFuncSetAttribute(dec_step_kernel, cudaFuncAttributeMaxDynamicSharedMemorySize, SMEM_BYTES);

    // launch #0: all preprocessing (fused steps start at launch #1)
    preproc_kernel<<<1024, 256>>>(enc_in, dec_in,
                                  enc_W0, enc_U0, enc_b0, enc_W1, enc_U1, enc_b1,
                                  dec_W0, dec_U0, dec_b0, dec_W1, dec_U1, dec_b1);

    for (int t = 0; t < TT; ++t)
        enc_step_kernel<<<NBLK, NTH, SMEM_BYTES>>>(t);

    for (int t = 0; t < TT; ++t)
        dec_step_kernel<<<NBLK, NTH, SMEM_BYTES>>>(t, dense_W, dense_b, out);
}